// round 1
// baseline (speedup 1.0000x reference)
#include <cuda_runtime.h>

// NT-Xent contrastive loss, fused.
//   zn = normalize(concat(z_i, z_j))            [8192, 128]
//   S_i = sum_j exp(2 * dot(zn_i, zn_j))        (all j, incl. self)
//   lse_i = log(S_i - e^2)                      (self-cosine == 1 exactly)
//   pos_i = 2 * dot(zn_i, zn_{(i+4096)%8192})
//   loss = sum_i (lse_i - pos_i) / 8192
// sim in [-2,2] always, so no online max is needed for the logsumexp.

#define N2      8192
#define NHALF   4096
#define D       128
#define TI      64
#define TJ      64
#define KT      64
#define STRIDE  65      // odd stride: <=2-way shared bank conflicts
#define INV_TEMP 2.0f

__device__ float g_zn[N2 * D];   // normalized embeddings (4 MB, L2-resident)
__device__ float g_lse[N2];
__device__ float g_pos[N2];

// ---------------------------------------------------------------------------
// 1) Row-normalize. One warp per row; lane loads float4 (32*4 = 128 elems).
// ---------------------------------------------------------------------------
__global__ void normalize_kernel(const float* __restrict__ zi,
                                 const float* __restrict__ zj) {
    int gw   = (blockIdx.x * blockDim.x + threadIdx.x) >> 5;
    int lane = threadIdx.x & 31;
    if (gw >= N2) return;
    const float* src = (gw < NHALF) ? (zi + (size_t)gw * D)
                                    : (zj + (size_t)(gw - NHALF) * D);
    float4 v = reinterpret_cast<const float4*>(src)[lane];
    float ss = v.x * v.x + v.y * v.y + v.z * v.z + v.w * v.w;
#pragma unroll
    for (int o = 16; o > 0; o >>= 1) ss += __shfl_xor_sync(0xffffffffu, ss, o);
    float inv = rsqrtf(ss);
    v.x *= inv; v.y *= inv; v.z *= inv; v.w *= inv;
    reinterpret_cast<float4*>(g_zn + (size_t)gw * D)[lane] = v;
}

// ---------------------------------------------------------------------------
// 2) Positive-pair similarities. One warp per row.
// ---------------------------------------------------------------------------
__global__ void pos_kernel() {
    int gw   = (blockIdx.x * blockDim.x + threadIdx.x) >> 5;
    int lane = threadIdx.x & 31;
    if (gw >= N2) return;
    int p = (gw + NHALF) & (N2 - 1);
    float4 a = reinterpret_cast<const float4*>(g_zn + (size_t)gw * D)[lane];
    float4 b = reinterpret_cast<const float4*>(g_zn + (size_t)p  * D)[lane];
    float d = a.x * b.x + a.y * b.y + a.z * b.z + a.w * b.w;
#pragma unroll
    for (int o = 16; o > 0; o >>= 1) d += __shfl_xor_sync(0xffffffffu, d, o);
    if (lane == 0) g_pos[gw] = d * INV_TEMP;
}

// ---------------------------------------------------------------------------
// 3) Fused GEMM + exp-rowsum + log. Block = 64 rows, loops over all 8192
//    columns in 64-wide tiles, K split into two 64-wide shared stages.
//    256 threads, 4x4 microtile per thread (16x16 thread grid).
// ---------------------------------------------------------------------------
__global__ __launch_bounds__(256, 1) void simlse_kernel() {
    __shared__ float As[TI][STRIDE];
    __shared__ float Bs[TJ][STRIDE];

    const int tid = threadIdx.x;
    const int tx  = tid & 15;   // column group (4 cols)
    const int ty  = tid >> 4;   // row group    (4 rows)
    const int r0  = blockIdx.x * TI;

    float rs0 = 0.f, rs1 = 0.f, rs2 = 0.f, rs3 = 0.f;

    for (int jt = 0; jt < N2 / TJ; ++jt) {
        float acc[4][4];
#pragma unroll
        for (int r = 0; r < 4; ++r)
#pragma unroll
            for (int c = 0; c < 4; ++c) acc[r][c] = 0.f;

        const int c0 = jt * TJ;
#pragma unroll 1
        for (int s = 0; s < 2; ++s) {
            __syncthreads();
            // Load 64x64 halves of A and B tiles (natural [row][k] layout).
#pragma unroll
            for (int c = 0; c < 4; ++c) {
                int f4  = tid + c * 256;     // 0..1023
                int row = f4 >> 4;
                int k4  = (f4 & 15) << 2;    // 0,4,...,60
                float4 va = *reinterpret_cast<const float4*>(
                    g_zn + (size_t)(r0 + row) * D + s * KT + k4);
                As[row][k4 + 0] = va.x; As[row][k4 + 1] = va.y;
                As[row][k4 + 2] = va.z; As[row][k4 + 3] = va.w;
                float4 vb = *reinterpret_cast<const float4*>(
                    g_zn + (size_t)(c0 + row) * D + s * KT + k4);
                Bs[row][k4 + 0] = vb.x; Bs[row][k4 + 1] = vb.y;
                Bs[row][k4 + 2] = vb.z; Bs[row][k4 + 3] = vb.w;
            }
            __syncthreads();

            const float* ap = &As[ty * 4][0];
            const float* bp = &Bs[tx * 4][0];
#pragma unroll 16
            for (int k = 0; k < KT; ++k) {
                float a0 = ap[k];
                float a1 = ap[k + 1 * STRIDE];
                float a2 = ap[k + 2 * STRIDE];
                float a3 = ap[k + 3 * STRIDE];
                float b0 = bp[k];
                float b1 = bp[k + 1 * STRIDE];
                float b2 = bp[k + 2 * STRIDE];
                float b3 = bp[k + 3 * STRIDE];
                acc[0][0] += a0 * b0; acc[0][1] += a0 * b1;
                acc[0][2] += a0 * b2; acc[0][3] += a0 * b3;
                acc[1][0] += a1 * b0; acc[1][1] += a1 * b1;
                acc[1][2] += a1 * b2; acc[1][3] += a1 * b3;
                acc[2][0] += a2 * b0; acc[2][1] += a2 * b1;
                acc[2][2] += a2 * b2; acc[2][3] += a2 * b3;
                acc[3][0] += a3 * b0; acc[3][1] += a3 * b1;
                acc[3][2] += a3 * b2; acc[3][3] += a3 * b3;
            }
        }
        // Epilogue: exp and per-row partial sums (sim = acc * 2, bounded by 2).
#pragma unroll
        for (int c = 0; c < 4; ++c) {
            rs0 += __expf(acc[0][c] * INV_TEMP);
            rs1 += __expf(acc[1][c] * INV_TEMP);
            rs2 += __expf(acc[2][c] * INV_TEMP);
            rs3 += __expf(acc[3][c] * INV_TEMP);
        }
    }

    // Reduce across the 16 tx lanes (same half-warp: lane = (ty&1)*16 + tx).
#pragma unroll
    for (int o = 8; o > 0; o >>= 1) {
        rs0 += __shfl_xor_sync(0xffffffffu, rs0, o);
        rs1 += __shfl_xor_sync(0xffffffffu, rs1, o);
        rs2 += __shfl_xor_sync(0xffffffffu, rs2, o);
        rs3 += __shfl_xor_sync(0xffffffffu, rs3, o);
    }
    if (tx == 0) {
        const float E2 = 7.38905609893065f;   // exp(2) = exp(self-sim/TEMP)
        int r = r0 + ty * 4;
        g_lse[r + 0] = logf(rs0 - E2);
        g_lse[r + 1] = logf(rs1 - E2);
        g_lse[r + 2] = logf(rs2 - E2);
        g_lse[r + 3] = logf(rs3 - E2);
    }
}

// ---------------------------------------------------------------------------
// 4) Deterministic final reduction (single block, fixed order).
// ---------------------------------------------------------------------------
__global__ void finish_kernel(float* __restrict__ out) {
    __shared__ float red[256];
    int tid = threadIdx.x;
    float s = 0.f;
    for (int i = tid; i < N2; i += 256) s += g_lse[i] - g_pos[i];
    red[tid] = s;
    __syncthreads();
#pragma unroll
    for (int o = 128; o > 0; o >>= 1) {
        if (tid < o) red[tid] += red[tid + o];
        __syncthreads();
    }
    if (tid == 0) out[0] = red[0] / (float)N2;
}

// ---------------------------------------------------------------------------
extern "C" void kernel_launch(void* const* d_in, const int* in_sizes, int n_in,
                              void* d_out, int out_size) {
    const float* zi = (const float*)d_in[0];
    const float* zj = (const float*)d_in[1];
    // (loss is symmetric under swapping z_i/z_j, so input order is safe)
    normalize_kernel<<<N2 / 8, 256>>>(zi, zj);
    pos_kernel<<<N2 / 8, 256>>>();
    simlse_kernel<<<N2 / TI, 256>>>();
    finish_kernel<<<1, 256>>>((float*)d_out);
}

// round 3
// speedup vs baseline: 12.0352x; 12.0352x over previous
#include <cuda_runtime.h>
#include <cuda_bf16.h>
#include <cstdint>
#include <cstring>

// NT-Xent contrastive loss, sm_103 (baseline ISA: mma.sync + ldmatrix + cp.async).
//   zn  = normalize(concat(z_i, z_j)) -> bf16 row-major [8192][128]
//   S_i = sum_j exp(2*dot(zn_i, zn_j))  (bf16 HMMA, fp32 accum, fused exp/rowsum)
//   loss = mean( log(S_i - e^2) - pos_i ),  pos in fp32 from raw inputs.

#define N2    8192
#define NHALF 4096
#define DD    128
#define NTILE 32          // 128-col tiles per CTA (4096 cols)
#define RSTRIDE 272       // smem bytes per 256B row (16B pad -> conflict-free ldmatrix)
#define TILE_SM (128 * RSTRIDE)

__device__ __align__(16) __nv_bfloat16 g_zn[(size_t)N2 * DD];
__device__ float g_S[2 * N2];
__device__ float g_pos[N2];

// ---------------- PTX helpers ----------------
__device__ __forceinline__ uint32_t smem_u32(const void* p) {
    uint32_t a;
    asm("{ .reg .u64 t; cvta.to.shared.u64 t, %1; cvt.u32.u64 %0, t; }" : "=r"(a) : "l"(p));
    return a;
}
__device__ __forceinline__ void cp16(uint32_t dst, const void* src) {
    asm volatile("cp.async.cg.shared.global [%0], [%1], 16;" :: "r"(dst), "l"(src));
}
#define CP_COMMIT() asm volatile("cp.async.commit_group;" ::: "memory")
#define CP_WAIT1()  asm volatile("cp.async.wait_group 1;" ::: "memory")

#define LDSM4(r0, r1, r2, r3, addr)                                            \
    asm volatile("ldmatrix.sync.aligned.m8n8.x4.shared.b16 {%0,%1,%2,%3}, [%4];" \
                 : "=r"(r0), "=r"(r1), "=r"(r2), "=r"(r3) : "r"(addr))

#define MMA16816(c, a, b0, b1)                                                 \
    asm volatile("mma.sync.aligned.m16n8k16.row.col.f32.bf16.bf16.f32 "        \
                 "{%0,%1,%2,%3}, {%4,%5,%6,%7}, {%8,%9}, {%0,%1,%2,%3};"       \
                 : "+f"((c)[0]), "+f"((c)[1]), "+f"((c)[2]), "+f"((c)[3])      \
                 : "r"((a)[0]), "r"((a)[1]), "r"((a)[2]), "r"((a)[3]),         \
                   "r"(b0), "r"(b1))

__device__ __forceinline__ float fast_ex2(float x) {
    float y; asm("ex2.approx.ftz.f32 %0, %1;" : "=f"(y) : "f"(x)); return y;
}

// ---------------- 1) prep: normalize -> bf16, pos in fp32 ----------------
__global__ void prep_kernel(const float* __restrict__ zi, const float* __restrict__ zj) {
    int w    = (blockIdx.x * blockDim.x + threadIdx.x) >> 5;   // pair 0..4095
    int lane = threadIdx.x & 31;
    if (w >= NHALF) return;
    float4 a = reinterpret_cast<const float4*>(zi + (size_t)w * DD)[lane];
    float4 b = reinterpret_cast<const float4*>(zj + (size_t)w * DD)[lane];
    float sa = a.x * a.x + a.y * a.y + a.z * a.z + a.w * a.w;
    float sb = b.x * b.x + b.y * b.y + b.z * b.z + b.w * b.w;
    float dp = a.x * b.x + a.y * b.y + a.z * b.z + a.w * b.w;
#pragma unroll
    for (int o = 16; o > 0; o >>= 1) {
        sa += __shfl_xor_sync(0xffffffffu, sa, o);
        sb += __shfl_xor_sync(0xffffffffu, sb, o);
        dp += __shfl_xor_sync(0xffffffffu, dp, o);
    }
    float ia = rsqrtf(sa), ib = rsqrtf(sb);
    if (lane == 0) {
        float p = 2.0f * dp * ia * ib;
        g_pos[w] = p; g_pos[w + NHALF] = p;
    }
    __nv_bfloat162 a0, a1, b0, b1;
    a0.x = __float2bfloat16_rn(a.x * ia); a0.y = __float2bfloat16_rn(a.y * ia);
    a1.x = __float2bfloat16_rn(a.z * ia); a1.y = __float2bfloat16_rn(a.w * ia);
    b0.x = __float2bfloat16_rn(b.x * ib); b0.y = __float2bfloat16_rn(b.y * ib);
    b1.x = __float2bfloat16_rn(b.z * ib); b1.y = __float2bfloat16_rn(b.w * ib);
    uint2 ua, ub;
    memcpy(&ua.x, &a0, 4); memcpy(&ua.y, &a1, 4);
    memcpy(&ub.x, &b0, 4); memcpy(&ub.y, &b1, 4);
    reinterpret_cast<uint2*>(g_zn + (size_t)w * DD)[lane] = ua;
    reinterpret_cast<uint2*>(g_zn + (size_t)(w + NHALF) * DD)[lane] = ub;
}

// ---------------- 2) fused HMMA GEMM + exp/rowsum ----------------
// grid = 128: band = bx>>1 (128 rows), split = bx&1 (4096 cols).
// 8 warps: warp tile 32m x 64n within the 128x128 CTA tile.
__device__ __forceinline__ void load_tile(uint32_t dstBase, const __nv_bfloat16* src,
                                          int tid) {
#pragma unroll
    for (int p = 0; p < 8; ++p) {
        int id = p * 256 + tid;          // 0..2047 chunks of 16B
        int row = id >> 4, ch = id & 15;
        cp16(dstBase + row * RSTRIDE + ch * 16,
             reinterpret_cast<const char*>(src) + row * 256 + ch * 16);
    }
}

__global__ __launch_bounds__(256, 1) void simlse_kernel() {
    extern __shared__ unsigned char smem[];
    const uint32_t sb = smem_u32(smem);
    const uint32_t smA  = sb;
    const uint32_t smB0 = sb + TILE_SM;

    const int tid  = threadIdx.x, wid = tid >> 5, lane = tid & 31;
    const int band = blockIdx.x >> 1, split = blockIdx.x & 1;
    const int r0   = band * 128;
    const int wm   = wid & 3;          // 4 warps along m (32 rows each)
    const int wn   = wid >> 2;         // 2 warps along n (64 cols each)

    // ldmatrix per-lane address offsets (bytes)
    const uint32_t aOff = (uint32_t)(lane & 15) * RSTRIDE + (uint32_t)((lane >> 4) << 4);
    const uint32_t bOff = (uint32_t)((lane & 7) + ((lane & 16) ? 8 : 0)) * RSTRIDE +
                          (uint32_t)((lane & 8) ? 16 : 0);

    // prologue: A tile + B tile 0 (group 0), B tile 1 (group 1)
    const __nv_bfloat16* gA = g_zn + (size_t)r0 * DD;
    const __nv_bfloat16* gB = g_zn + (size_t)split * 4096 * DD;
    load_tile(smA, gA, tid);
    load_tile(smB0, gB, tid);
    CP_COMMIT();
    load_tile(smB0 + TILE_SM, gB + (size_t)128 * DD, tid);
    CP_COMMIT();

    const float C = 2.8853900817779268f;   // 2 * log2(e)
    float rs[2][2] = {{0.f, 0.f}, {0.f, 0.f}};   // [mb][lo/hi] row partial sums

    const uint32_t aBase = smA + (uint32_t)(wm * 32) * RSTRIDE + aOff;

    for (int it = 0; it < NTILE; ++it) {
        CP_WAIT1();
        __syncthreads();

        const uint32_t bBase = smB0 + (uint32_t)(it & 1) * TILE_SM +
                               (uint32_t)(wn * 64) * RSTRIDE + bOff;
        float acc[2][8][4];
#pragma unroll
        for (int mb = 0; mb < 2; ++mb)
#pragma unroll
            for (int nb = 0; nb < 8; ++nb)
#pragma unroll
                for (int r = 0; r < 4; ++r) acc[mb][nb][r] = 0.f;

#pragma unroll
        for (int ks = 0; ks < 8; ++ks) {
            uint32_t a[2][4], b[4][4];
#pragma unroll
            for (int mb = 0; mb < 2; ++mb)
                LDSM4(a[mb][0], a[mb][1], a[mb][2], a[mb][3],
                      aBase + (uint32_t)(mb * 16) * RSTRIDE + (uint32_t)(ks * 32));
#pragma unroll
            for (int n2 = 0; n2 < 4; ++n2)
                LDSM4(b[n2][0], b[n2][1], b[n2][2], b[n2][3],
                      bBase + (uint32_t)(n2 * 16) * RSTRIDE + (uint32_t)(ks * 32));
#pragma unroll
            for (int mb = 0; mb < 2; ++mb)
#pragma unroll
                for (int n2 = 0; n2 < 4; ++n2) {
                    MMA16816(acc[mb][2 * n2 + 0], a[mb], b[n2][0], b[n2][1]);
                    MMA16816(acc[mb][2 * n2 + 1], a[mb], b[n2][2], b[n2][3]);
                }
        }
        __syncthreads();
        if (it + 2 < NTILE)
            load_tile(smB0 + (uint32_t)(it & 1) * TILE_SM,
                      gB + (size_t)(it + 2) * 128 * DD, tid);
        CP_COMMIT();

        // epilogue: exp + per-row partial sums (sim = acc*2, in [-2,2])
#pragma unroll
        for (int mb = 0; mb < 2; ++mb) {
            float lo = 0.f, hi = 0.f;
#pragma unroll
            for (int nb = 0; nb < 8; ++nb) {
                lo += fast_ex2(acc[mb][nb][0] * C) + fast_ex2(acc[mb][nb][1] * C);
                hi += fast_ex2(acc[mb][nb][2] * C) + fast_ex2(acc[mb][nb][3] * C);
            }
            rs[mb][0] += lo; rs[mb][1] += hi;
        }
    }

    // reduce across the 4 lanes of each quad (they share the same rows)
#pragma unroll
    for (int mb = 0; mb < 2; ++mb)
#pragma unroll
        for (int h = 0; h < 2; ++h) {
            rs[mb][h] += __shfl_xor_sync(0xffffffffu, rs[mb][h], 1);
            rs[mb][h] += __shfl_xor_sync(0xffffffffu, rs[mb][h], 2);
        }

    __syncthreads();   // done with smem tiles; reuse as partial buffer
    float* part = reinterpret_cast<float*>(smem);   // [2][128]
    if ((lane & 3) == 0) {
        int rbase = wm * 32 + (lane >> 2);
#pragma unroll
        for (int mb = 0; mb < 2; ++mb) {
            part[wn * 128 + rbase + mb * 16 + 0] = rs[mb][0];
            part[wn * 128 + rbase + mb * 16 + 8] = rs[mb][1];
        }
    }
    __syncthreads();
    if (tid < 128)
        g_S[split * N2 + r0 + tid] = part[tid] + part[128 + tid];
}

// ---------------- 3) finish ----------------
__global__ void finish_kernel(float* __restrict__ out) {
    __shared__ float red[1024];
    const int t = threadIdx.x;
    const float E2 = 7.3890560989306495f;  // exp(2): self-similarity term
    float s = 0.f;
#pragma unroll
    for (int u = 0; u < 2; ++u) {
        int i = t * 8 + u * 4;
        float4 s0 = *reinterpret_cast<const float4*>(g_S + i);
        float4 s1 = *reinterpret_cast<const float4*>(g_S + N2 + i);
        float4 pp = *reinterpret_cast<const float4*>(g_pos + i);
        s += (logf(s0.x + s1.x - E2) - pp.x);
        s += (logf(s0.y + s1.y - E2) - pp.y);
        s += (logf(s0.z + s1.z - E2) - pp.z);
        s += (logf(s0.w + s1.w - E2) - pp.w);
    }
    red[t] = s;
    __syncthreads();
#pragma unroll
    for (int o = 512; o > 0; o >>= 1) {
        if (t < o) red[t] += red[t + o];
        __syncthreads();
    }
    if (t == 0) out[0] = red[0] * (1.0f / (float)N2);
}

// ---------------- launch ----------------
extern "C" void kernel_launch(void* const* d_in, const int* in_sizes, int n_in,
                              void* d_out, int out_size) {
    const float* zi = (const float*)d_in[0];
    const float* zj = (const float*)d_in[1];
    cudaFuncSetAttribute(simlse_kernel, cudaFuncAttributeMaxDynamicSharedMemorySize,
                         3 * TILE_SM);
    prep_kernel<<<NHALF / 8, 256>>>(zi, zj);
    simlse_kernel<<<128, 256, 3 * TILE_SM>>>();
    finish_kernel<<<1, 1024>>>((float*)d_out);
}

// round 4
// speedup vs baseline: 12.4024x; 1.0305x over previous
#include <cuda_runtime.h>
#include <cuda_bf16.h>
#include <cuda_fp16.h>
#include <cstdint>
#include <cstring>

// NT-Xent contrastive loss, sm_103 baseline ISA (mma.sync + ldmatrix + cp.async).
//   g_znA = normalize(z) * 2*log2(e)  (bf16)   -> MMA acc is directly log2-domain
//   g_znB = normalize(z)              (bf16)
//   S_i = sum_j exp2(acc_ij)  via h2exp2 (f16x2 MUFU), fp32 row sums
//   loss = mean( log(S_i - e^2) - pos_i ), pos in fp32 from raw inputs.

#define N2    8192
#define NHALF 4096
#define DD    128
#define NTILE 32
#define RSTRIDE 272                 // 256B row + 16B pad: conflict-free ldmatrix
#define TILE_SM (128 * RSTRIDE)     // 34816 B

__device__ __align__(16) __nv_bfloat16 g_znA[(size_t)N2 * DD];  // scaled by 2*log2(e)
__device__ __align__(16) __nv_bfloat16 g_znB[(size_t)N2 * DD];  // unscaled
__device__ float g_S[2 * N2];
__device__ float g_pos[N2];

// ---------------- PTX helpers ----------------
__device__ __forceinline__ uint32_t smem_u32(const void* p) {
    uint32_t a;
    asm("{ .reg .u64 t; cvta.to.shared.u64 t, %1; cvt.u32.u64 %0, t; }" : "=r"(a) : "l"(p));
    return a;
}
__device__ __forceinline__ void cp16(uint32_t dst, const void* src) {
    asm volatile("cp.async.cg.shared.global [%0], [%1], 16;" :: "r"(dst), "l"(src));
}
#define CP_COMMIT() asm volatile("cp.async.commit_group;" ::: "memory")
#define CP_WAIT1()  asm volatile("cp.async.wait_group 1;" ::: "memory")
#define CP_WAIT0()  asm volatile("cp.async.wait_group 0;" ::: "memory")

#define LDSM4(r0, r1, r2, r3, addr)                                              \
    asm volatile("ldmatrix.sync.aligned.m8n8.x4.shared.b16 {%0,%1,%2,%3}, [%4];" \
                 : "=r"(r0), "=r"(r1), "=r"(r2), "=r"(r3) : "r"(addr))

#define MMA16816(c, a, b0, b1)                                                 \
    asm volatile("mma.sync.aligned.m16n8k16.row.col.f32.bf16.bf16.f32 "        \
                 "{%0,%1,%2,%3}, {%4,%5,%6,%7}, {%8,%9}, {%0,%1,%2,%3};"       \
                 : "+f"((c)[0]), "+f"((c)[1]), "+f"((c)[2]), "+f"((c)[3])      \
                 : "r"((a)[0]), "r"((a)[1]), "r"((a)[2]), "r"((a)[3]),         \
                   "r"(b0), "r"(b1))

__device__ __forceinline__ float fast_lg2(float x) {
    float y; asm("lg2.approx.f32 %0, %1;" : "=f"(y) : "f"(x)); return y;
}

// ---------------- 1) prep ----------------
__global__ void prep_kernel(const float* __restrict__ zi, const float* __restrict__ zj) {
    int w    = (blockIdx.x * blockDim.x + threadIdx.x) >> 5;
    int lane = threadIdx.x & 31;
    if (w >= NHALF) return;
    float4 a = reinterpret_cast<const float4*>(zi + (size_t)w * DD)[lane];
    float4 b = reinterpret_cast<const float4*>(zj + (size_t)w * DD)[lane];
    float sa = a.x * a.x + a.y * a.y + a.z * a.z + a.w * a.w;
    float sb = b.x * b.x + b.y * b.y + b.z * b.z + b.w * b.w;
    float dp = a.x * b.x + a.y * b.y + a.z * b.z + a.w * b.w;
#pragma unroll
    for (int o = 16; o > 0; o >>= 1) {
        sa += __shfl_xor_sync(0xffffffffu, sa, o);
        sb += __shfl_xor_sync(0xffffffffu, sb, o);
        dp += __shfl_xor_sync(0xffffffffu, dp, o);
    }
    float ia = rsqrtf(sa), ib = rsqrtf(sb);
    if (lane == 0) {
        float p = 2.0f * dp * ia * ib;
        g_pos[w] = p; g_pos[w + NHALF] = p;
    }
    const float CA = 2.8853900817779268f;   // 2 * log2(e)
    float iaC = ia * CA, ibC = ib * CA;
    __nv_bfloat162 p0, p1;
    uint2 u;
    // A copy (scaled)
    p0.x = __float2bfloat16_rn(a.x * iaC); p0.y = __float2bfloat16_rn(a.y * iaC);
    p1.x = __float2bfloat16_rn(a.z * iaC); p1.y = __float2bfloat16_rn(a.w * iaC);
    memcpy(&u.x, &p0, 4); memcpy(&u.y, &p1, 4);
    reinterpret_cast<uint2*>(g_znA + (size_t)w * DD)[lane] = u;
    p0.x = __float2bfloat16_rn(b.x * ibC); p0.y = __float2bfloat16_rn(b.y * ibC);
    p1.x = __float2bfloat16_rn(b.z * ibC); p1.y = __float2bfloat16_rn(b.w * ibC);
    memcpy(&u.x, &p0, 4); memcpy(&u.y, &p1, 4);
    reinterpret_cast<uint2*>(g_znA + (size_t)(w + NHALF) * DD)[lane] = u;
    // B copy (unscaled)
    p0.x = __float2bfloat16_rn(a.x * ia); p0.y = __float2bfloat16_rn(a.y * ia);
    p1.x = __float2bfloat16_rn(a.z * ia); p1.y = __float2bfloat16_rn(a.w * ia);
    memcpy(&u.x, &p0, 4); memcpy(&u.y, &p1, 4);
    reinterpret_cast<uint2*>(g_znB + (size_t)w * DD)[lane] = u;
    p0.x = __float2bfloat16_rn(b.x * ib); p0.y = __float2bfloat16_rn(b.y * ib);
    p1.x = __float2bfloat16_rn(b.z * ib); p1.y = __float2bfloat16_rn(b.w * ib);
    memcpy(&u.x, &p0, 4); memcpy(&u.y, &p1, 4);
    reinterpret_cast<uint2*>(g_znB + (size_t)(w + NHALF) * DD)[lane] = u;
}

// ---------------- 2) fused HMMA GEMM + exp2/rowsum ----------------
// grid=128: band=bx>>1 (128 rows), split=bx&1 (4096 cols).
// 8 warps = wm(0..1, 64 rows) x wn(0..3, 32 cols). A fragments register-resident.
__device__ __forceinline__ void load_tile(uint32_t dstBase, const __nv_bfloat16* src,
                                          int tid) {
#pragma unroll
    for (int p = 0; p < 8; ++p) {
        int id = p * 256 + tid;
        int row = id >> 4, ch = id & 15;
        cp16(dstBase + row * RSTRIDE + ch * 16,
             reinterpret_cast<const char*>(src) + row * 256 + ch * 16);
    }
}

__global__ __launch_bounds__(256, 1) void simlse_kernel() {
    extern __shared__ unsigned char smem[];
    const uint32_t sb   = smem_u32(smem);
    const uint32_t smA  = sb;
    const uint32_t smB0 = sb + TILE_SM;

    const int tid  = threadIdx.x, wid = tid >> 5, lane = tid & 31;
    const int band = blockIdx.x >> 1, split = blockIdx.x & 1;
    const int r0   = band * 128;
    const int wn   = wid & 3;          // 4 col groups (32 cols)
    const int wm   = wid >> 2;         // 2 row groups (64 rows)

    const uint32_t aOff = (uint32_t)(lane & 15) * RSTRIDE + (uint32_t)((lane >> 4) << 4);
    const uint32_t bOff = (uint32_t)((lane & 7) + ((lane & 16) ? 8 : 0)) * RSTRIDE +
                          (uint32_t)((lane & 8) ? 16 : 0);

    const __nv_bfloat16* gB = g_znB + (size_t)split * 4096 * DD;

    // prologue: A tile + B0 (group0), B1 (group1)
    load_tile(smA,  g_znA + (size_t)r0 * DD, tid);
    load_tile(smB0, gB, tid);
    CP_COMMIT();
    load_tile(smB0 + TILE_SM, gB + (size_t)128 * DD, tid);
    CP_COMMIT();
    CP_WAIT1();
    __syncthreads();

    // A fragments: 64 rows x 128 k, resident all kernel (128 regs)
    uint32_t afr[4][8][4];
    {
        const uint32_t aBase = smA + (uint32_t)(wm * 64) * RSTRIDE + aOff;
#pragma unroll
        for (int mb = 0; mb < 4; ++mb)
#pragma unroll
            for (int ks = 0; ks < 8; ++ks)
                LDSM4(afr[mb][ks][0], afr[mb][ks][1], afr[mb][ks][2], afr[mb][ks][3],
                      aBase + (uint32_t)(mb * 16) * RSTRIDE + (uint32_t)(ks * 32));
    }

    __half2 zero2 = __float2half2_rn(0.f);
    __half2 sum01[4] = {zero2, zero2, zero2, zero2};   // rows r   (c0,c1)
    __half2 sum23[4] = {zero2, zero2, zero2, zero2};   // rows r+8 (c2,c3)
    float frow[4][2] = {{0.f,0.f},{0.f,0.f},{0.f,0.f},{0.f,0.f}};

    for (int it = 0; it < NTILE; ++it) {
        const uint32_t bBase = smB0 + (uint32_t)(it & 1) * TILE_SM +
                               (uint32_t)(wn * 32) * RSTRIDE + bOff;
#pragma unroll
        for (int np = 0; np < 2; ++np) {
            uint32_t bfr[8][4];
#pragma unroll
            for (int ks = 0; ks < 8; ++ks)
                LDSM4(bfr[ks][0], bfr[ks][1], bfr[ks][2], bfr[ks][3],
                      bBase + (uint32_t)(np * 16) * RSTRIDE + (uint32_t)(ks * 32));

            float acc[4][2][4];
#pragma unroll
            for (int mb = 0; mb < 4; ++mb)
#pragma unroll
                for (int nb = 0; nb < 2; ++nb)
#pragma unroll
                    for (int r = 0; r < 4; ++r) acc[mb][nb][r] = 0.f;

#pragma unroll
            for (int ks = 0; ks < 8; ++ks)
#pragma unroll
                for (int mb = 0; mb < 4; ++mb) {
                    MMA16816(acc[mb][0], afr[mb][ks], bfr[ks][0], bfr[ks][1]);
                    MMA16816(acc[mb][1], afr[mb][ks], bfr[ks][2], bfr[ks][3]);
                }

            // exp2 epilogue: acc already log2-domain (A pre-scaled)
#pragma unroll
            for (int mb = 0; mb < 4; ++mb) {
#pragma unroll
                for (int nb = 0; nb < 2; ++nb) {
                    __half2 e01 = h2exp2(__floats2half2_rn(acc[mb][nb][0], acc[mb][nb][1]));
                    __half2 e23 = h2exp2(__floats2half2_rn(acc[mb][nb][2], acc[mb][nb][3]));
                    sum01[mb] = __hadd2(sum01[mb], e01);
                    sum23[mb] = __hadd2(sum23[mb], e23);
                }
            }
        }
        // flush packed sums to fp32 once per iter (lane sums <= ~60, fp16-safe)
#pragma unroll
        for (int mb = 0; mb < 4; ++mb) {
            float2 f0 = __half22float2(sum01[mb]);
            float2 f1 = __half22float2(sum23[mb]);
            frow[mb][0] += f0.x + f0.y;
            frow[mb][1] += f1.x + f1.y;
            sum01[mb] = zero2; sum23[mb] = zero2;
        }

        __syncthreads();
        if (it + 2 < NTILE)
            load_tile(smB0 + (uint32_t)(it & 1) * TILE_SM,
                      gB + (size_t)(it + 2) * 128 * DD, tid);
        CP_COMMIT();
        if (it + 1 < NTILE) { CP_WAIT1(); __syncthreads(); }
    }

    // quad reduction: lanes q*4..q*4+3 hold same rows, different cols
#pragma unroll
    for (int mb = 0; mb < 4; ++mb)
#pragma unroll
        for (int h = 0; h < 2; ++h) {
            frow[mb][h] += __shfl_xor_sync(0xffffffffu, frow[mb][h], 1);
            frow[mb][h] += __shfl_xor_sync(0xffffffffu, frow[mb][h], 2);
        }

    __syncthreads();
    float* part = reinterpret_cast<float*>(smem);   // [4 wn][128 rows]
    if ((lane & 3) == 0) {
        int q = lane >> 2;
#pragma unroll
        for (int mb = 0; mb < 4; ++mb) {
            part[wn * 128 + wm * 64 + mb * 16 + q + 0] = frow[mb][0];
            part[wn * 128 + wm * 64 + mb * 16 + q + 8] = frow[mb][1];
        }
    }
    __syncthreads();
    if (tid < 128)
        g_S[split * N2 + r0 + tid] =
            part[tid] + part[128 + tid] + part[256 + tid] + part[384 + tid];
}

// ---------------- 3) finish ----------------
__global__ void finish_kernel(float* __restrict__ out) {
    __shared__ float red[32];
    const int t = threadIdx.x, lane = t & 31, w = t >> 5;
    const float E2  = 7.3890560989306495f;
    const float LN2 = 0.6931471805599453f;
    float s = 0.f;
#pragma unroll
    for (int u = 0; u < 2; ++u) {
        int i = t * 8 + u * 4;
        float4 s0 = *reinterpret_cast<const float4*>(g_S + i);
        float4 s1 = *reinterpret_cast<const float4*>(g_S + N2 + i);
        float4 pp = *reinterpret_cast<const float4*>(g_pos + i);
        s += (fast_lg2(s0.x + s1.x - E2) * LN2 - pp.x);
        s += (fast_lg2(s0.y + s1.y - E2) * LN2 - pp.y);
        s += (fast_lg2(s0.z + s1.z - E2) * LN2 - pp.z);
        s += (fast_lg2(s0.w + s1.w - E2) * LN2 - pp.w);
    }
#pragma unroll
    for (int o = 16; o > 0; o >>= 1) s += __shfl_xor_sync(0xffffffffu, s, o);
    if (lane == 0) red[w] = s;
    __syncthreads();
    if (w == 0) {
        float v = red[lane];
#pragma unroll
        for (int o = 16; o > 0; o >>= 1) v += __shfl_xor_sync(0xffffffffu, v, o);
        if (lane == 0) out[0] = v * (1.0f / (float)N2);
    }
}

// ---------------- launch ----------------
extern "C" void kernel_launch(void* const* d_in, const int* in_sizes, int n_in,
                              void* d_out, int out_size) {
    const float* zi = (const float*)d_in[0];
    const float* zj = (const float*)d_in[1];
    cudaFuncSetAttribute(simlse_kernel, cudaFuncAttributeMaxDynamicSharedMemorySize,
                         3 * TILE_SM);
    prep_kernel<<<NHALF / 8, 256>>>(zi, zj);
    simlse_kernel<<<128, 256, 3 * TILE_SM>>>();
    finish_kernel<<<1, 1024>>>((float*)d_out);
}